// round 10
// baseline (speedup 1.0000x reference)
#include <cuda_runtime.h>
#include <math.h>

#define DD 128
#define MAXN 50000
#define MAXE 800000
#define SCAN_TILE 1024

// ---------------- device scratch (device-code-only symbols) ----------------
__device__ float g_as_u[MAXN], g_ad_u[MAXN], g_as_i[MAXN], g_ad_i[MAXN];
__device__ int   g_off_ui[MAXN + 1], g_off_iu[MAXN + 1];
__device__ int   g_cur_ui[MAXN], g_cur_iu[MAXN];
__device__ int   g_psrc_ui[MAXE], g_psrc_iu[MAXE];
__device__ float g_pnorm_ui[MAXE], g_pnorm_iu[MAXE];
__device__ float g_w_u[MAXN], g_w_i[MAXN];
__device__ float g_Wt[2 * DD * DD];   // Wt[k][j]: k<128 -> W1[j][k], else W2[j][k-128]
__device__ int   g_part[128];

// ---------------- kernels ----------------

__global__ void __launch_bounds__(256) zero_counts_kernel(int NI, int NU) {
    int i = blockIdx.x * blockDim.x + threadIdx.x;
    if (i <= NI) g_off_ui[i] = 0;
    if (i <= NU) g_off_iu[i] = 0;
}

__global__ void __launch_bounds__(256) attn_dots_kernel(
    const float* __restrict__ fu, const float* __restrict__ fi,
    const float* __restrict__ aw, int NU, int NI) {
    int warp = (blockIdx.x * blockDim.x + threadIdx.x) >> 5;
    int lane = threadIdx.x & 31;
    int total = NU + NI;
    if (warp >= total) return;
    const float* f = (warp < NU) ? (fu + (size_t)warp * DD)
                                 : (fi + (size_t)(warp - NU) * DD);
    float4 x  = ((const float4*)f)[lane];
    float4 wl = ((const float4*)aw)[lane];
    float4 wh = ((const float4*)aw)[32 + lane];
    float slo = x.x * wl.x + x.y * wl.y + x.z * wl.z + x.w * wl.w;
    float shi = x.x * wh.x + x.y * wh.y + x.z * wh.z + x.w * wh.w;
#pragma unroll
    for (int o = 16; o; o >>= 1) {
        slo += __shfl_xor_sync(0xffffffffu, slo, o);
        shi += __shfl_xor_sync(0xffffffffu, shi, o);
    }
    if (lane == 0) {
        if (warp < NU) { g_as_u[warp] = slo; g_ad_u[warp] = shi; }
        else           { g_as_i[warp - NU] = slo; g_ad_i[warp - NU] = shi; }
    }
}

__global__ void __launch_bounds__(256) count_kernel(
    const int* __restrict__ src_u, const int* __restrict__ dst_i, int E) {
    int e = blockIdx.x * blockDim.x + threadIdx.x;
    if (e >= E) return;
    atomicAdd(&g_off_ui[dst_i[e]], 1);
    atomicAdd(&g_off_iu[src_u[e]], 1);
}

__global__ void __launch_bounds__(256) scan_phase1(int NI, int NU, int nb_ui) {
    int which = (blockIdx.x >= nb_ui);
    int* arr = which ? g_off_iu : g_off_ui;
    int n    = which ? NU : NI;
    int tile = which ? (blockIdx.x - nb_ui) : blockIdx.x;
    int tid  = threadIdx.x;
    int base = tile * SCAN_TILE + tid * 4;

    int v0 = (base + 0 < n) ? arr[base + 0] : 0;
    int v1 = (base + 1 < n) ? arr[base + 1] : 0;
    int v2 = (base + 2 < n) ? arr[base + 2] : 0;
    int v3 = (base + 3 < n) ? arr[base + 3] : 0;
    int tsum = v0 + v1 + v2 + v3;

    int lane = tid & 31, wid = tid >> 5;
    int incl = tsum;
#pragma unroll
    for (int o = 1; o < 32; o <<= 1) {
        int t = __shfl_up_sync(0xffffffffu, incl, o);
        if (lane >= o) incl += t;
    }
    __shared__ int wsum[8];
    __shared__ int woff[8];
    if (lane == 31) wsum[wid] = incl;
    __syncthreads();
    if (tid == 0) {
        int s = 0;
#pragma unroll
        for (int w = 0; w < 8; w++) { woff[w] = s; s += wsum[w]; }
        g_part[blockIdx.x] = s;
    }
    __syncthreads();
    int excl = woff[wid] + incl - tsum;
    if (base + 0 < n) arr[base + 0] = excl;
    if (base + 1 < n) arr[base + 1] = excl + v0;
    if (base + 2 < n) arr[base + 2] = excl + v0 + v1;
    if (base + 3 < n) arr[base + 3] = excl + v0 + v1 + v2;
}

__global__ void __launch_bounds__(128) scan_phase2(int NI, int NU, int nb_ui, int nb_iu) {
    __shared__ int s[128];
    int tid = threadIdx.x;
    int seg = tid >> 6;
    int idx = tid & 63;
    int nb  = seg ? nb_iu : nb_ui;
    int v = (idx < nb) ? g_part[seg ? (nb_ui + idx) : idx] : 0;
    s[tid] = v;
    __syncthreads();
#pragma unroll
    for (int o = 1; o < 64; o <<= 1) {
        int t = (idx >= o) ? s[tid - o] : 0;
        __syncthreads();
        s[tid] += t;
        __syncthreads();
    }
    if (idx < nb) g_part[seg ? (nb_ui + idx) : idx] = s[tid] - v;
    if (idx == 63) {
        if (seg == 0) g_off_ui[NI] = s[63];
        else          g_off_iu[NU] = s[127];
    }
}

__global__ void __launch_bounds__(256) scan_phase3(int NI, int NU, int nb_ui) {
    int which = (blockIdx.x >= nb_ui);
    int* arr = which ? g_off_iu : g_off_ui;
    int* cur = which ? g_cur_iu : g_cur_ui;
    int n    = which ? NU : NI;
    int tile = which ? (blockIdx.x - nb_ui) : blockIdx.x;
    int off  = g_part[blockIdx.x];
    int base = tile * SCAN_TILE + threadIdx.x * 4;
#pragma unroll
    for (int j = 0; j < 4; j++) {
        int i = base + j;
        if (i < n) { int v = arr[i] + off; arr[i] = v; cur[i] = v; }
    }
}

__global__ void __launch_bounds__(256) scatter_kernel(
    const int* __restrict__ src_u, const int* __restrict__ dst_i,
    const float* __restrict__ norm_ui, const float* __restrict__ norm_iu, int E) {
    int e = blockIdx.x * blockDim.x + threadIdx.x;
    if (e >= E) return;
    int u = src_u[e], d = dst_i[e];
    int p = atomicAdd(&g_cur_ui[d], 1);
    g_psrc_ui[p] = u;
    g_pnorm_ui[p] = norm_ui[e];
    int q = atomicAdd(&g_cur_iu[u], 1);
    g_psrc_iu[q] = d;
    g_pnorm_iu[q] = norm_iu[e];
}

// one warp per destination node; warps [0,NI) -> item dsts, [NI,NI+NU) -> user dsts.
__global__ void __launch_bounds__(128) agg_kernel(
    const float* __restrict__ feat_user, const float* __restrict__ feat_item,
    float* A_item, float* A_user, int NI, int NU) {
    int w = blockIdx.x * (blockDim.x >> 5) + (threadIdx.x >> 5);
    int lane = threadIdx.x & 31;
    if (w >= NI + NU) return;

    int node;
    const int* off; const int* psrc; const float* pnorm;
    const float* fsrc; const float* fdst; const float* as_src; const float* ad_dst;
    float* outA; float* outw;
    if (w < NI) {
        node = w;
        off = g_off_ui; psrc = g_psrc_ui; pnorm = g_pnorm_ui;
        fsrc = feat_user; fdst = feat_item; as_src = g_as_u; ad_dst = g_ad_i;
        outA = A_item; outw = g_w_i;
    } else {
        node = w - NI;
        off = g_off_iu; psrc = g_psrc_iu; pnorm = g_pnorm_iu;
        fsrc = feat_item; fdst = feat_user; as_src = g_as_i; ad_dst = g_ad_u;
        outA = A_user; outw = g_w_u;
    }

    float4 xd = ((const float4*)fdst)[(size_t)node * 32 + lane];
    float adv = ad_dst[node];
    int o0 = off[node], o1 = off[node + 1];

    float den = 0.f;
    for (int k = o0 + lane; k < o1; k += 32) {
        int s = psrc[k];
        float a = as_src[s] + adv;
        a = (a < 0.f) ? 0.2f * a : a;
        den += __expf(a);
    }
#pragma unroll
    for (int o = 16; o; o >>= 1) den += __shfl_xor_sync(0xffffffffu, den, o);
    float rden = (den > 0.f) ? (1.f / den) : 0.f;

    // pass 2: two-edge unroll for gather MLP
    float Ax = 0.f, Ay = 0.f, Az = 0.f, Aw = 0.f, ws = 0.f;
    float Bx = 0.f, By = 0.f, Bz = 0.f, Bw = 0.f, ws2 = 0.f;
    const float4* fs4 = (const float4*)fsrc;
    int k = o0;
    for (; k + 1 < o1; k += 2) {
        int s0 = psrc[k], s1 = psrc[k + 1];
        float n0 = pnorm[k], n1 = pnorm[k + 1];
        float a0 = as_src[s0] + adv; a0 = (a0 < 0.f) ? 0.2f * a0 : a0;
        float a1 = as_src[s1] + adv; a1 = (a1 < 0.f) ? 0.2f * a1 : a1;
        float c0 = __expf(a0) * rden * n0;
        float c1 = __expf(a1) * rden * n1;
        float4 x0 = fs4[(size_t)s0 * 32 + lane];
        float4 x1 = fs4[(size_t)s1 * 32 + lane];
        Ax += c0 * x0.x; Ay += c0 * x0.y; Az += c0 * x0.z; Aw += c0 * x0.w; ws += c0;
        Bx += c1 * x1.x; By += c1 * x1.y; Bz += c1 * x1.z; Bw += c1 * x1.w; ws2 += c1;
    }
    if (k < o1) {
        int s0 = psrc[k];
        float n0 = pnorm[k];
        float a0 = as_src[s0] + adv; a0 = (a0 < 0.f) ? 0.2f * a0 : a0;
        float c0 = __expf(a0) * rden * n0;
        float4 x0 = fs4[(size_t)s0 * 32 + lane];
        Ax += c0 * x0.x; Ay += c0 * x0.y; Az += c0 * x0.z; Aw += c0 * x0.w; ws += c0;
    }
    Ax += Bx; Ay += By; Az += Bz; Aw += Bw; ws += ws2;

    float4 A = make_float4(Ax + xd.x, Ay + xd.y, Az + xd.z, Aw + xd.w);
    ((float4*)outA)[(size_t)node * 32 + lane] = A;
    if (lane == 0) outw[node] = ws;
}

__global__ void __launch_bounds__(256) transW_kernel(
    const float* __restrict__ W1, const float* __restrict__ W2) {
    int idx = blockIdx.x * blockDim.x + threadIdx.x;
    if (idx >= 2 * DD * DD) return;
    int k = idx >> 7, j = idx & 127;
    g_Wt[idx] = (k < DD) ? W1[j * DD + k] : W2[j * DD + (k - DD)];
}

// out[row] = leaky( A'@W1^T + ((A'-xd).*xd)@W2^T + b1 + w*(b1+b2) ), L2-normalized.
// One launch: blocks [0,nbU) -> users, rest -> items. In-place over d_out.
// 128-row tile/block, 8x8 microtile, K=256 in 16-chunks with REGISTER PREFETCH:
// chunk k+1's global loads are issued right after the post-store sync and
// consumed a full compute-phase later, hiding L2/DRAM latency behind 1024 FFMAs.
// All per-thread state register-resident (literal indices only).
#define FMA_ROW(i, ai)                                                     \
    accLo[i].x += (ai) * w0.x; accLo[i].y += (ai) * w0.y;                  \
    accLo[i].z += (ai) * w0.z; accLo[i].w += (ai) * w0.w;                  \
    accHi[i].x += (ai) * w1.x; accHi[i].y += (ai) * w1.y;                  \
    accHi[i].z += (ai) * w1.z; accHi[i].w += (ai) * w1.w;

#define LEAKY1(h) ((h) < 0.f ? 0.2f * (h) : (h))

__global__ void __launch_bounds__(256) gemm_finish_kernel(
    float* A_user, float* A_item,
    const float* __restrict__ feat_user, const float* __restrict__ feat_item,
    const float* __restrict__ b1, const float* __restrict__ b2,
    int NU, int NI, int nbU) {

    const float* Aregion; const float* feat; const float* wv; float* outp;
    int row0, M;
    if ((int)blockIdx.x < nbU) {
        Aregion = A_user; feat = feat_user; wv = g_w_u; outp = A_user;
        row0 = blockIdx.x * 128; M = NU;
    } else {
        Aregion = A_item; feat = feat_item; wv = g_w_i; outp = A_item;
        row0 = (blockIdx.x - nbU) * 128; M = NI;
    }

    __shared__ float Gs[16][128];
    __shared__ float Ws[16][128];
    __shared__ float rpart[128][17];
    __shared__ float rscale[128];

    int tx = threadIdx.x;
    int tm = (tx >> 4) * 8;
    int tng = tx & 15;
    int tn = tng * 8;

    // load/store index decomposition (each thread owns row gm, 8 consecutive k)
    int gm  = tx >> 1;                // 0..127 (row within tile)
    int gkq = (tx & 1) * 2;           // k-quad 0 or 2 (two quads per thread)
    int wk0 = (tx * 2) >> 5;          // Ws row for s=0
    int wj0 = (tx * 2) & 31;          // Ws col-quad for s=0
    int wk1 = (tx * 2 + 1) >> 5;
    int wj1 = (tx * 2 + 1) & 31;
    bool mvalid = (row0 + gm < M);

    float4 accLo[8], accHi[8];
#pragma unroll
    for (int i = 0; i < 8; i++) {
        accLo[i] = make_float4(0.f, 0.f, 0.f, 0.f);
        accHi[i] = make_float4(0.f, 0.f, 0.f, 0.f);
    }

    const float* Abase = Aregion + (size_t)row0 * DD;
    const float* Fbase = feat    + (size_t)row0 * DD;

    float4 pa0, pa1, pf0, pf1, pw0, pw1;
    pa0 = pa1 = pf0 = pf1 = make_float4(0.f, 0.f, 0.f, 0.f);

#define LOAD_CHUNK(kc_) {                                                     \
        int kl_ = (kc_) & 127;                                                \
        bool sec_ = ((kc_) >= 128);                                           \
        if (mvalid) {                                                         \
            pa0 = *(const float4*)(Abase + (size_t)gm * DD + kl_ + gkq * 4);  \
            pa1 = *(const float4*)(Abase + (size_t)gm * DD + kl_ + gkq * 4 + 4);\
            if (sec_) {                                                       \
                pf0 = *(const float4*)(Fbase + (size_t)gm * DD + kl_ + gkq * 4);\
                pf1 = *(const float4*)(Fbase + (size_t)gm * DD + kl_ + gkq * 4 + 4);\
            }                                                                 \
        }                                                                     \
        pw0 = *(const float4*)(g_Wt + (size_t)((kc_) + wk0) * DD + wj0 * 4);  \
        pw1 = *(const float4*)(g_Wt + (size_t)((kc_) + wk1) * DD + wj1 * 4);  \
    }

#define STORE_CHUNK(kc_) {                                                    \
        bool sec_ = ((kc_) >= 128);                                           \
        float4 v0 = pa0, v1 = pa1;                                            \
        if (sec_) {                                                           \
            v0.x = (pa0.x - pf0.x) * pf0.x; v0.y = (pa0.y - pf0.y) * pf0.y;   \
            v0.z = (pa0.z - pf0.z) * pf0.z; v0.w = (pa0.w - pf0.w) * pf0.w;   \
            v1.x = (pa1.x - pf1.x) * pf1.x; v1.y = (pa1.y - pf1.y) * pf1.y;   \
            v1.z = (pa1.z - pf1.z) * pf1.z; v1.w = (pa1.w - pf1.w) * pf1.w;   \
        }                                                                     \
        if (!mvalid) { v0 = make_float4(0.f,0.f,0.f,0.f); v1 = v0; }          \
        Gs[gkq * 4 + 0][gm] = v0.x;  Gs[gkq * 4 + 1][gm] = v0.y;              \
        Gs[gkq * 4 + 2][gm] = v0.z;  Gs[gkq * 4 + 3][gm] = v0.w;              \
        Gs[gkq * 4 + 4][gm] = v1.x;  Gs[gkq * 4 + 5][gm] = v1.y;              \
        Gs[gkq * 4 + 6][gm] = v1.z;  Gs[gkq * 4 + 7][gm] = v1.w;              \
        *(float4*)&Ws[wk0][wj0 * 4] = pw0;                                    \
        *(float4*)&Ws[wk1][wj1 * 4] = pw1;                                    \
    }

    LOAD_CHUNK(0)
    for (int kc = 0; kc < 256; kc += 16) {
        STORE_CHUNK(kc)
        __syncthreads();
        if (kc + 16 < 256) LOAD_CHUNK(kc + 16)
#pragma unroll
        for (int kk = 0; kk < 16; kk++) {
            float4 a0 = *(const float4*)&Gs[kk][tm];
            float4 a1 = *(const float4*)&Gs[kk][tm + 4];
            float4 w0 = *(const float4*)&Ws[kk][tn];
            float4 w1 = *(const float4*)&Ws[kk][tn + 4];
            FMA_ROW(0, a0.x) FMA_ROW(1, a0.y) FMA_ROW(2, a0.z) FMA_ROW(3, a0.w)
            FMA_ROW(4, a1.x) FMA_ROW(5, a1.y) FMA_ROW(6, a1.z) FMA_ROW(7, a1.w)
        }
        __syncthreads();
    }

    // epilogue: bias, leaky, row L2-norm, store (all register-resident)
    float4 b1lo = *(const float4*)(b1 + tn);
    float4 b1hi = *(const float4*)(b1 + tn + 4);
    float4 b2lo = *(const float4*)(b2 + tn);
    float4 b2hi = *(const float4*)(b2 + tn + 4);
    float4 pqlo = make_float4(b1lo.x + b2lo.x, b1lo.y + b2lo.y,
                              b1lo.z + b2lo.z, b1lo.w + b2lo.w);
    float4 pqhi = make_float4(b1hi.x + b2hi.x, b1hi.y + b2hi.y,
                              b1hi.z + b2hi.z, b1hi.w + b2hi.w);

#pragma unroll
    for (int i = 0; i < 8; i++) {
        int row = row0 + tm + i;
        float w = (row < M) ? wv[row] : 0.f;
        float4 lo = accLo[i], hi = accHi[i];
        lo.x = LEAKY1(lo.x + b1lo.x + w * pqlo.x);
        lo.y = LEAKY1(lo.y + b1lo.y + w * pqlo.y);
        lo.z = LEAKY1(lo.z + b1lo.z + w * pqlo.z);
        lo.w = LEAKY1(lo.w + b1lo.w + w * pqlo.w);
        hi.x = LEAKY1(hi.x + b1hi.x + w * pqhi.x);
        hi.y = LEAKY1(hi.y + b1hi.y + w * pqhi.y);
        hi.z = LEAKY1(hi.z + b1hi.z + w * pqhi.z);
        hi.w = LEAKY1(hi.w + b1hi.w + w * pqhi.w);
        accLo[i] = lo; accHi[i] = hi;
        float ssq = lo.x * lo.x + lo.y * lo.y + lo.z * lo.z + lo.w * lo.w
                  + hi.x * hi.x + hi.y * hi.y + hi.z * hi.z + hi.w * hi.w;
        rpart[tm + i][tng] = ssq;
    }
    __syncthreads();
    if (tx < 128) {
        float s = 0.f;
#pragma unroll
        for (int t = 0; t < 16; t++) s += rpart[tx][t];
        rscale[tx] = 1.f / fmaxf(sqrtf(s), 1e-12f);
    }
    __syncthreads();
#pragma unroll
    for (int i = 0; i < 8; i++) {
        int row = row0 + tm + i;
        if (row >= M) continue;
        float sc = rscale[tm + i];
        float4 lo = accLo[i], hi = accHi[i];
        lo.x *= sc; lo.y *= sc; lo.z *= sc; lo.w *= sc;
        hi.x *= sc; hi.y *= sc; hi.z *= sc; hi.w *= sc;
        *(float4*)(outp + (size_t)row * DD + tn) = lo;
        *(float4*)(outp + (size_t)row * DD + tn + 4) = hi;
    }
}

// ---------------- launch ----------------
extern "C" void kernel_launch(void* const* d_in, const int* in_sizes, int n_in,
                              void* d_out, int out_size) {
    (void)n_in; (void)out_size;
    const float* feat_user = (const float*)d_in[0];
    const float* feat_item = (const float*)d_in[1];
    const int*   src_u     = (const int*)d_in[2];
    const int*   dst_i     = (const int*)d_in[3];
    const float* norm_ui   = (const float*)d_in[4];
    const float* norm_iu   = (const float*)d_in[5];
    const float* W1_w      = (const float*)d_in[6];
    const float* W1_b      = (const float*)d_in[7];
    const float* W2_w      = (const float*)d_in[8];
    const float* W2_b      = (const float*)d_in[9];
    const float* attn_w    = (const float*)d_in[10];

    int NU = in_sizes[0] / DD;
    int NI = in_sizes[1] / DD;
    int E  = in_sizes[2];
    float* out = (float*)d_out;
    float* A_user = out;                      // rows [0, NU)
    float* A_item = out + (size_t)NU * DD;    // rows [NU, NU+NI)

    int maxn1 = ((NU > NI ? NU : NI) + 1);
    zero_counts_kernel<<<(maxn1 + 255) / 256, 256>>>(NI, NU);

    {
        int warps = NU + NI;
        attn_dots_kernel<<<(warps * 32 + 255) / 256, 256>>>(feat_user, feat_item,
                                                            attn_w, NU, NI);
    }

    count_kernel<<<(E + 255) / 256, 256>>>(src_u, dst_i, E);

    int nb_ui = (NI + SCAN_TILE - 1) / SCAN_TILE;
    int nb_iu = (NU + SCAN_TILE - 1) / SCAN_TILE;
    scan_phase1<<<nb_ui + nb_iu, 256>>>(NI, NU, nb_ui);
    scan_phase2<<<1, 128>>>(NI, NU, nb_ui, nb_iu);
    scan_phase3<<<nb_ui + nb_iu, 256>>>(NI, NU, nb_ui);

    scatter_kernel<<<(E + 255) / 256, 256>>>(src_u, dst_i, norm_ui, norm_iu, E);

    agg_kernel<<<(NI + NU + 3) / 4, 128>>>(feat_user, feat_item,
                                           A_item, A_user, NI, NU);

    transW_kernel<<<(2 * DD * DD + 255) / 256, 256>>>(W1_w, W2_w);

    int nbU = (NU + 127) / 128, nbI = (NI + 127) / 128;
    gemm_finish_kernel<<<nbU + nbI, 256>>>(A_user, A_item, feat_user, feat_item,
                                           W1_b, W2_b, NU, NI, nbU);
}

// round 13
// speedup vs baseline: 1.0681x; 1.0681x over previous
#include <cuda_runtime.h>
#include <cuda_pipeline.h>
#include <math.h>

#define DD 128
#define MAXN 50000
#define MAXE 800000
#define SCAN_TILE 1024

// ---------------- device scratch (device-code-only symbols) ----------------
__device__ float g_as_u[MAXN], g_ad_u[MAXN], g_as_i[MAXN], g_ad_i[MAXN];
__device__ int   g_off_ui[MAXN + 1], g_off_iu[MAXN + 1];
__device__ int   g_cur_ui[MAXN], g_cur_iu[MAXN];
__device__ int   g_psrc_ui[MAXE], g_psrc_iu[MAXE];
__device__ float g_pnorm_ui[MAXE], g_pnorm_iu[MAXE];
__device__ float g_w_u[MAXN], g_w_i[MAXN];
__device__ float g_Wt[2 * DD * DD];   // Wt[k][j]: k<128 -> W1[j][k], else W2[j][k-128]
__device__ int   g_part[128];

// ---------------- kernels ----------------

__global__ void __launch_bounds__(256) zero_counts_kernel(int NI, int NU) {
    int i = blockIdx.x * blockDim.x + threadIdx.x;
    if (i <= NI) g_off_ui[i] = 0;
    if (i <= NU) g_off_iu[i] = 0;
}

__global__ void __launch_bounds__(256) attn_dots_kernel(
    const float* __restrict__ fu, const float* __restrict__ fi,
    const float* __restrict__ aw, int NU, int NI) {
    int warp = (blockIdx.x * blockDim.x + threadIdx.x) >> 5;
    int lane = threadIdx.x & 31;
    int total = NU + NI;
    if (warp >= total) return;
    const float* f = (warp < NU) ? (fu + (size_t)warp * DD)
                                 : (fi + (size_t)(warp - NU) * DD);
    float4 x  = ((const float4*)f)[lane];
    float4 wl = ((const float4*)aw)[lane];
    float4 wh = ((const float4*)aw)[32 + lane];
    float slo = x.x * wl.x + x.y * wl.y + x.z * wl.z + x.w * wl.w;
    float shi = x.x * wh.x + x.y * wh.y + x.z * wh.z + x.w * wh.w;
#pragma unroll
    for (int o = 16; o; o >>= 1) {
        slo += __shfl_xor_sync(0xffffffffu, slo, o);
        shi += __shfl_xor_sync(0xffffffffu, shi, o);
    }
    if (lane == 0) {
        if (warp < NU) { g_as_u[warp] = slo; g_ad_u[warp] = shi; }
        else           { g_as_i[warp - NU] = slo; g_ad_i[warp - NU] = shi; }
    }
}

__global__ void __launch_bounds__(256) count_kernel(
    const int* __restrict__ src_u, const int* __restrict__ dst_i, int E) {
    int e = blockIdx.x * blockDim.x + threadIdx.x;
    if (e >= E) return;
    atomicAdd(&g_off_ui[dst_i[e]], 1);
    atomicAdd(&g_off_iu[src_u[e]], 1);
}

__global__ void __launch_bounds__(256) scan_phase1(int NI, int NU, int nb_ui) {
    int which = (blockIdx.x >= nb_ui);
    int* arr = which ? g_off_iu : g_off_ui;
    int n    = which ? NU : NI;
    int tile = which ? (blockIdx.x - nb_ui) : blockIdx.x;
    int tid  = threadIdx.x;
    int base = tile * SCAN_TILE + tid * 4;

    int v0 = (base + 0 < n) ? arr[base + 0] : 0;
    int v1 = (base + 1 < n) ? arr[base + 1] : 0;
    int v2 = (base + 2 < n) ? arr[base + 2] : 0;
    int v3 = (base + 3 < n) ? arr[base + 3] : 0;
    int tsum = v0 + v1 + v2 + v3;

    int lane = tid & 31, wid = tid >> 5;
    int incl = tsum;
#pragma unroll
    for (int o = 1; o < 32; o <<= 1) {
        int t = __shfl_up_sync(0xffffffffu, incl, o);
        if (lane >= o) incl += t;
    }
    __shared__ int wsum[8];
    __shared__ int woff[8];
    if (lane == 31) wsum[wid] = incl;
    __syncthreads();
    if (tid == 0) {
        int s = 0;
#pragma unroll
        for (int w = 0; w < 8; w++) { woff[w] = s; s += wsum[w]; }
        g_part[blockIdx.x] = s;
    }
    __syncthreads();
    int excl = woff[wid] + incl - tsum;
    if (base + 0 < n) arr[base + 0] = excl;
    if (base + 1 < n) arr[base + 1] = excl + v0;
    if (base + 2 < n) arr[base + 2] = excl + v0 + v1;
    if (base + 3 < n) arr[base + 3] = excl + v0 + v1 + v2;
}

__global__ void __launch_bounds__(128) scan_phase2(int NI, int NU, int nb_ui, int nb_iu) {
    __shared__ int s[128];
    int tid = threadIdx.x;
    int seg = tid >> 6;
    int idx = tid & 63;
    int nb  = seg ? nb_iu : nb_ui;
    int v = (idx < nb) ? g_part[seg ? (nb_ui + idx) : idx] : 0;
    s[tid] = v;
    __syncthreads();
#pragma unroll
    for (int o = 1; o < 64; o <<= 1) {
        int t = (idx >= o) ? s[tid - o] : 0;
        __syncthreads();
        s[tid] += t;
        __syncthreads();
    }
    if (idx < nb) g_part[seg ? (nb_ui + idx) : idx] = s[tid] - v;
    if (idx == 63) {
        if (seg == 0) g_off_ui[NI] = s[63];
        else          g_off_iu[NU] = s[127];
    }
}

__global__ void __launch_bounds__(256) scan_phase3(int NI, int NU, int nb_ui) {
    int which = (blockIdx.x >= nb_ui);
    int* arr = which ? g_off_iu : g_off_ui;
    int* cur = which ? g_cur_iu : g_cur_ui;
    int n    = which ? NU : NI;
    int tile = which ? (blockIdx.x - nb_ui) : blockIdx.x;
    int off  = g_part[blockIdx.x];
    int base = tile * SCAN_TILE + threadIdx.x * 4;
#pragma unroll
    for (int j = 0; j < 4; j++) {
        int i = base + j;
        if (i < n) { int v = arr[i] + off; arr[i] = v; cur[i] = v; }
    }
}

__global__ void __launch_bounds__(256) scatter_kernel(
    const int* __restrict__ src_u, const int* __restrict__ dst_i,
    const float* __restrict__ norm_ui, const float* __restrict__ norm_iu, int E) {
    int e = blockIdx.x * blockDim.x + threadIdx.x;
    if (e >= E) return;
    int u = src_u[e], d = dst_i[e];
    int p = atomicAdd(&g_cur_ui[d], 1);
    g_psrc_ui[p] = u;
    g_pnorm_ui[p] = norm_ui[e];
    int q = atomicAdd(&g_cur_iu[u], 1);
    g_psrc_iu[q] = d;
    g_pnorm_iu[q] = norm_iu[e];
}

// one warp per destination node; warps [0,NI) -> item dsts, [NI,NI+NU) -> user dsts.
__global__ void __launch_bounds__(128) agg_kernel(
    const float* __restrict__ feat_user, const float* __restrict__ feat_item,
    float* A_item, float* A_user, int NI, int NU) {
    int w = blockIdx.x * (blockDim.x >> 5) + (threadIdx.x >> 5);
    int lane = threadIdx.x & 31;
    if (w >= NI + NU) return;

    int node;
    const int* off; const int* psrc; const float* pnorm;
    const float* fsrc; const float* fdst; const float* as_src; const float* ad_dst;
    float* outA; float* outw;
    if (w < NI) {
        node = w;
        off = g_off_ui; psrc = g_psrc_ui; pnorm = g_pnorm_ui;
        fsrc = feat_user; fdst = feat_item; as_src = g_as_u; ad_dst = g_ad_i;
        outA = A_item; outw = g_w_i;
    } else {
        node = w - NI;
        off = g_off_iu; psrc = g_psrc_iu; pnorm = g_pnorm_iu;
        fsrc = feat_item; fdst = feat_user; as_src = g_as_i; ad_dst = g_ad_u;
        outA = A_user; outw = g_w_u;
    }

    float4 xd = ((const float4*)fdst)[(size_t)node * 32 + lane];
    float adv = ad_dst[node];
    int o0 = off[node], o1 = off[node + 1];

    float den = 0.f;
    for (int k = o0 + lane; k < o1; k += 32) {
        int s = psrc[k];
        float a = as_src[s] + adv;
        a = (a < 0.f) ? 0.2f * a : a;
        den += __expf(a);
    }
#pragma unroll
    for (int o = 16; o; o >>= 1) den += __shfl_xor_sync(0xffffffffu, den, o);
    float rden = (den > 0.f) ? (1.f / den) : 0.f;

    float Ax = 0.f, Ay = 0.f, Az = 0.f, Aw = 0.f, ws = 0.f;
    float Bx = 0.f, By = 0.f, Bz = 0.f, Bw = 0.f, ws2 = 0.f;
    const float4* fs4 = (const float4*)fsrc;
    int k = o0;
    for (; k + 1 < o1; k += 2) {
        int s0 = psrc[k], s1 = psrc[k + 1];
        float n0 = pnorm[k], n1 = pnorm[k + 1];
        float a0 = as_src[s0] + adv; a0 = (a0 < 0.f) ? 0.2f * a0 : a0;
        float a1 = as_src[s1] + adv; a1 = (a1 < 0.f) ? 0.2f * a1 : a1;
        float c0 = __expf(a0) * rden * n0;
        float c1 = __expf(a1) * rden * n1;
        float4 x0 = fs4[(size_t)s0 * 32 + lane];
        float4 x1 = fs4[(size_t)s1 * 32 + lane];
        Ax += c0 * x0.x; Ay += c0 * x0.y; Az += c0 * x0.z; Aw += c0 * x0.w; ws += c0;
        Bx += c1 * x1.x; By += c1 * x1.y; Bz += c1 * x1.z; Bw += c1 * x1.w; ws2 += c1;
    }
    if (k < o1) {
        int s0 = psrc[k];
        float n0 = pnorm[k];
        float a0 = as_src[s0] + adv; a0 = (a0 < 0.f) ? 0.2f * a0 : a0;
        float c0 = __expf(a0) * rden * n0;
        float4 x0 = fs4[(size_t)s0 * 32 + lane];
        Ax += c0 * x0.x; Ay += c0 * x0.y; Az += c0 * x0.z; Aw += c0 * x0.w; ws += c0;
    }
    Ax += Bx; Ay += By; Az += Bz; Aw += Bw; ws += ws2;

    float4 A = make_float4(Ax + xd.x, Ay + xd.y, Az + xd.z, Aw + xd.w);
    ((float4*)outA)[(size_t)node * 32 + lane] = A;
    if (lane == 0) outw[node] = ws;
}

__global__ void __launch_bounds__(256) transW_kernel(
    const float* __restrict__ W1, const float* __restrict__ W2) {
    int idx = blockIdx.x * blockDim.x + threadIdx.x;
    if (idx >= 2 * DD * DD) return;
    int k = idx >> 7, j = idx & 127;
    g_Wt[idx] = (k < DD) ? W1[j * DD + k] : W2[j * DD + (k - DD)];
}

// out[row] = leaky( A'@W1^T + ((A'-xd).*xd)@W2^T + b1 + w*(b1+b2) ), L2-normalized.
// R7 structure + cp.async double-buffered W tiles (zero extra registers).
#define FMA_ROW(i, ai)                                                     \
    accLo[i].x += (ai) * w0.x; accLo[i].y += (ai) * w0.y;                  \
    accLo[i].z += (ai) * w0.z; accLo[i].w += (ai) * w0.w;                  \
    accHi[i].x += (ai) * w1.x; accHi[i].y += (ai) * w1.y;                  \
    accHi[i].z += (ai) * w1.z; accHi[i].w += (ai) * w1.w;

#define LEAKY1(h) ((h) < 0.f ? 0.2f * (h) : (h))

__global__ void __launch_bounds__(256) gemm_finish_kernel(
    float* A_user, float* A_item,
    const float* __restrict__ feat_user, const float* __restrict__ feat_item,
    const float* __restrict__ b1, const float* __restrict__ b2,
    int NU, int NI, int nbU) {

    const float* Aregion; const float* feat; const float* wv; float* outp;
    int row0, M;
    if ((int)blockIdx.x < nbU) {
        Aregion = A_user; feat = feat_user; wv = g_w_u; outp = A_user;
        row0 = blockIdx.x * 128; M = NU;
    } else {
        Aregion = A_item; feat = feat_item; wv = g_w_i; outp = A_item;
        row0 = (blockIdx.x - nbU) * 128; M = NI;
    }

    __shared__ float Gs[16][128];
    __shared__ float Wsb[2][16][128];
    __shared__ float rpart[128][17];
    __shared__ float rscale[128];

    int tx = threadIdx.x;
    int tm = (tx >> 4) * 8;
    int tng = tx & 15;
    int tn = tng * 8;

    // W copy indices (same decomposition as R7's W load)
    int wk0 = (tx * 2) >> 5,     wj0 = (tx * 2) & 31;
    int wk1 = (tx * 2 + 1) >> 5, wj1 = (tx * 2 + 1) & 31;

    float4 accLo[8], accHi[8];
#pragma unroll
    for (int i = 0; i < 8; i++) {
        accLo[i] = make_float4(0.f, 0.f, 0.f, 0.f);
        accHi[i] = make_float4(0.f, 0.f, 0.f, 0.f);
    }

    const float* Abase = Aregion + (size_t)row0 * DD;
    const float* Fbase = feat    + (size_t)row0 * DD;

    // prologue: async-copy W chunk 0 into buffer 0
    __pipeline_memcpy_async(&Wsb[0][wk0][wj0 * 4],
                            g_Wt + (size_t)wk0 * DD + wj0 * 4, 16);
    __pipeline_memcpy_async(&Wsb[0][wk1][wj1 * 4],
                            g_Wt + (size_t)wk1 * DD + wj1 * 4, 16);
    __pipeline_commit();

    for (int kc = 0; kc < 256; kc += 16) {
        int buf = (kc >> 4) & 1;
        int kl = kc & 127;
        bool second = (kc >= 128);
#pragma unroll
        for (int s = 0; s < 2; s++) {
            int id = tx * 2 + s;
            int m = id >> 2, kq = id & 3;
            float4 v = make_float4(0.f, 0.f, 0.f, 0.f);
            if (row0 + m < M) {
                float4 a = *(const float4*)(Abase + (size_t)m * DD + kl + kq * 4);
                if (second) {
                    float4 f = *(const float4*)(Fbase + (size_t)m * DD + kl + kq * 4);
                    v.x = (a.x - f.x) * f.x; v.y = (a.y - f.y) * f.y;
                    v.z = (a.z - f.z) * f.z; v.w = (a.w - f.w) * f.w;
                } else {
                    v = a;
                }
            }
            Gs[kq * 4 + 0][m] = v.x;
            Gs[kq * 4 + 1][m] = v.y;
            Gs[kq * 4 + 2][m] = v.z;
            Gs[kq * 4 + 3][m] = v.w;
        }
        if (kc + 16 < 256) {
            // async-copy next W chunk into the other buffer
            __pipeline_memcpy_async(&Wsb[buf ^ 1][wk0][wj0 * 4],
                                    g_Wt + (size_t)(kc + 16 + wk0) * DD + wj0 * 4, 16);
            __pipeline_memcpy_async(&Wsb[buf ^ 1][wk1][wj1 * 4],
                                    g_Wt + (size_t)(kc + 16 + wk1) * DD + wj1 * 4, 16);
            __pipeline_commit();
            __pipeline_wait_prior(1);   // current chunk's W group done
        } else {
            __pipeline_wait_prior(0);
        }
        __syncthreads();
#pragma unroll
        for (int kk = 0; kk < 16; kk++) {
            float4 a0 = *(const float4*)&Gs[kk][tm];
            float4 a1 = *(const float4*)&Gs[kk][tm + 4];
            float4 w0 = *(const float4*)&Wsb[buf][kk][tn];
            float4 w1 = *(const float4*)&Wsb[buf][kk][tn + 4];
            FMA_ROW(0, a0.x) FMA_ROW(1, a0.y) FMA_ROW(2, a0.z) FMA_ROW(3, a0.w)
            FMA_ROW(4, a1.x) FMA_ROW(5, a1.y) FMA_ROW(6, a1.z) FMA_ROW(7, a1.w)
        }
        __syncthreads();
    }

    float4 b1lo = *(const float4*)(b1 + tn);
    float4 b1hi = *(const float4*)(b1 + tn + 4);
    float4 b2lo = *(const float4*)(b2 + tn);
    float4 b2hi = *(const float4*)(b2 + tn + 4);
    float4 pqlo = make_float4(b1lo.x + b2lo.x, b1lo.y + b2lo.y,
                              b1lo.z + b2lo.z, b1lo.w + b2lo.w);
    float4 pqhi = make_float4(b1hi.x + b2hi.x, b1hi.y + b2hi.y,
                              b1hi.z + b2hi.z, b1hi.w + b2hi.w);

#pragma unroll
    for (int i = 0; i < 8; i++) {
        int row = row0 + tm + i;
        float w = (row < M) ? wv[row] : 0.f;
        float4 lo = accLo[i], hi = accHi[i];
        lo.x = LEAKY1(lo.x + b1lo.x + w * pqlo.x);
        lo.y = LEAKY1(lo.y + b1lo.y + w * pqlo.y);
        lo.z = LEAKY1(lo.z + b1lo.z + w * pqlo.z);
        lo.w = LEAKY1(lo.w + b1lo.w + w * pqlo.w);
        hi.x = LEAKY1(hi.x + b1hi.x + w * pqhi.x);
        hi.y = LEAKY1(hi.y + b1hi.y + w * pqhi.y);
        hi.z = LEAKY1(hi.z + b1hi.z + w * pqhi.z);
        hi.w = LEAKY1(hi.w + b1hi.w + w * pqhi.w);
        accLo[i] = lo; accHi[i] = hi;
        float ssq = lo.x * lo.x + lo.y * lo.y + lo.z * lo.z + lo.w * lo.w
                  + hi.x * hi.x + hi.y * hi.y + hi.z * hi.z + hi.w * hi.w;
        rpart[tm + i][tng] = ssq;
    }
    __syncthreads();
    if (tx < 128) {
        float s = 0.f;
#pragma unroll
        for (int t = 0; t < 16; t++) s += rpart[tx][t];
        rscale[tx] = 1.f / fmaxf(sqrtf(s), 1e-12f);
    }
    __syncthreads();
#pragma unroll
    for (int i = 0; i < 8; i++) {
        int row = row0 + tm + i;
        if (row >= M) continue;
        float sc = rscale[tm + i];
        float4 lo = accLo[i], hi = accHi[i];
        lo.x *= sc; lo.y *= sc; lo.z *= sc; lo.w *= sc;
        hi.x *= sc; hi.y *= sc; hi.z *= sc; hi.w *= sc;
        *(float4*)(outp + (size_t)row * DD + tn) = lo;
        *(float4*)(outp + (size_t)row * DD + tn + 4) = hi;
    }
}

// ---------------- launch ----------------
extern "C" void kernel_launch(void* const* d_in, const int* in_sizes, int n_in,
                              void* d_out, int out_size) {
    (void)n_in; (void)out_size;
    const float* feat_user = (const float*)d_in[0];
    const float* feat_item = (const float*)d_in[1];
    const int*   src_u     = (const int*)d_in[2];
    const int*   dst_i     = (const int*)d_in[3];
    const float* norm_ui   = (const float*)d_in[4];
    const float* norm_iu   = (const float*)d_in[5];
    const float* W1_w      = (const float*)d_in[6];
    const float* W1_b      = (const float*)d_in[7];
    const float* W2_w      = (const float*)d_in[8];
    const float* W2_b      = (const float*)d_in[9];
    const float* attn_w    = (const float*)d_in[10];

    int NU = in_sizes[0] / DD;
    int NI = in_sizes[1] / DD;
    int E  = in_sizes[2];
    float* out = (float*)d_out;
    float* A_user = out;                      // rows [0, NU)
    float* A_item = out + (size_t)NU * DD;    // rows [NU, NU+NI)

    int maxn1 = ((NU > NI ? NU : NI) + 1);
    zero_counts_kernel<<<(maxn1 + 255) / 256, 256>>>(NI, NU);

    {
        int warps = NU + NI;
        attn_dots_kernel<<<(warps * 32 + 255) / 256, 256>>>(feat_user, feat_item,
                                                            attn_w, NU, NI);
    }

    count_kernel<<<(E + 255) / 256, 256>>>(src_u, dst_i, E);

    int nb_ui = (NI + SCAN_TILE - 1) / SCAN_TILE;
    int nb_iu = (NU + SCAN_TILE - 1) / SCAN_TILE;
    scan_phase1<<<nb_ui + nb_iu, 256>>>(NI, NU, nb_ui);
    scan_phase2<<<1, 128>>>(NI, NU, nb_ui, nb_iu);
    scan_phase3<<<nb_ui + nb_iu, 256>>>(NI, NU, nb_ui);

    scatter_kernel<<<(E + 255) / 256, 256>>>(src_u, dst_i, norm_ui, norm_iu, E);

    agg_kernel<<<(NI + NU + 3) / 4, 128>>>(feat_user, feat_item,
                                           A_item, A_user, NI, NU);

    transW_kernel<<<(2 * DD * DD + 255) / 256, 256>>>(W1_w, W2_w);

    int nbU = (NU + 127) / 128, nbI = (NI + 127) / 128;
    gemm_finish_kernel<<<nbU + nbI, 256>>>(A_user, A_item, feat_user, feat_item,
                                           W1_b, W2_b, NU, NI, nbU);
}